// round 11
// baseline (speedup 1.0000x reference)
#include <cuda_runtime.h>
#include <cstdint>
#include <math.h>

// B=256 T=20 NOBJ=5 D=2048 P=1000 IN=2018 H=512

// ------------------------- device scratch -------------------------
__device__ float g_MH [2048*512];
__device__ float g_MO [2048*512];
__device__ float g_CHv[512];
__device__ float g_COv[512];
__device__ float g_Y  [30720*512];
__device__ float g_G1 [30720*512];
__device__ float g_Z  [30720*512];
__device__ float g_SG [30720*512];
__device__ float g_HN [5120*512];
__device__ float g_ON [25600*1024];
__device__ float g_XPH[5120*512];
__device__ float g_HR0[5120*512];
__device__ float g_HR1[5120*512];
__device__ float g_XPO[25600*1024];
__device__ float g_OR0[25600*1024];
__device__ float g_OR1[25600*1024];
__device__ float g_A1H[5120*512];
__device__ float g_A1O[25600*512];
__device__ int   g_off[257];
// pre-rounded (tf32-in-fp32) weight copies (small buffers only)
__device__ float g_Wphr [2048000];
__device__ float g_Wpor [2048000];
__device__ float g_Wg1r [1033216];
__device__ float g_Wg2r [262144];
__device__ float g_sWihr[524288];
__device__ float g_aWihr[2097152];
__device__ float g_chW1r[262144];
__device__ float g_coW1r[524288];

struct GemmP {
  const float* A; const float* B; float* C;
  int M, N, K;
  int lda, ldb, ldc;
  const float* bias1;
};

__device__ __forceinline__ float to_tf32(float x){
  float r; asm("cvt.rna.tf32.f32 %0, %1;" : "=f"(r) : "f"(x)); return r;
}

__device__ __forceinline__ void mma8(float (&c)[4], const float (&a)[4], const float (&b)[2]){
  asm volatile(
    "mma.sync.aligned.m16n8k8.row.col.f32.tf32.tf32.f32 "
    "{%0,%1,%2,%3}, {%4,%5,%6,%7}, {%8,%9}, {%0,%1,%2,%3};\n"
    : "+f"(c[0]), "+f"(c[1]), "+f"(c[2]), "+f"(c[3])
    : "r"(__float_as_uint(a[0])), "r"(__float_as_uint(a[1])),
      "r"(__float_as_uint(a[2])), "r"(__float_as_uint(a[3])),
      "r"(__float_as_uint(b[0])), "r"(__float_as_uint(b[1])));
}

__device__ __forceinline__ void cp16(float* smem_ptr, const float* gmem, bool pred){
  unsigned int s = (unsigned int)__cvta_generic_to_shared(smem_ptr);
  int sz = pred ? 16 : 0;
  asm volatile("cp.async.cg.shared.global [%0], [%1], 16, %2;\n"
               :: "r"(s), "l"(gmem), "r"(sz));
}
#define CP_COMMIT() asm volatile("cp.async.commit_group;\n")
#define CP_WAIT1()  asm volatile("cp.async.wait_group 1;\n")

// grid-stride tf32 rounding copy (n % 4 == 0)
__global__ void roundcopy_k(const float* __restrict__ src, float* __restrict__ dst, int n){
  int i = (blockIdx.x*blockDim.x + threadIdx.x)*4;
  int stride = gridDim.x*blockDim.x*4;
  for (; i+3 < n; i += stride){
    float4 v = *(const float4*)(src+i);
    float4 w; w.x=to_tf32(v.x); w.y=to_tf32(v.y); w.z=to_tf32(v.z); w.w=to_tf32(v.w);
    *(float4*)(dst+i) = w;
  }
}

// ---------------------------------------------------------------------------
// 3-stage cp.async tf32 GEMM. BM=128, BN=128, BK=16; 8 warps (2m x 4n).
//  AMODE: 0 A[m*lda+k], 1 human-RF rows, 2 obj-RF rows, 3 A[k*lda+m]
//  BMODE: 0 B[k*ldb+n], 1 B[n*ldb+k]
//  CMODE: 0 crow=m, 1 crow=m*6, 2 obj row map
//  EPI:   0 none, 1 bias+relu, 2 round output to tf32
//  ACVT:  1 -> convert A-frags to tf32 in-register (A not pre-rounded)
//  B (and A when ACVT=0) must be pre-rounded tf32-in-fp32.
//  Row-major tile: [128][20] ; K-major tile: [16][136]. One barrier/iter.
// ---------------------------------------------------------------------------
template<int AMODE,int BMODE,int CMODE,int EPI,int ACVT>
__global__ __launch_bounds__(256,2) void fgemm_k(GemmP p)
{
  constexpr bool AROW = (AMODE != 3);
  constexpr bool BROW = (BMODE == 1);
  constexpr int ASZ = AROW ? 128*20 : 16*136;
  constexpr int BSZ = BROW ? 128*20 : 16*136;
  extern __shared__ float dsm[];
  float* As = dsm;              // [3][ASZ]
  float* Bs = dsm + 3*ASZ;      // [3][BSZ]

  const int m0 = blockIdx.y * 128;
  const int n0 = blockIdx.x * 128;
  const int tid = threadIdx.x, wid = tid>>5, lane = tid&31;
  const int gr = lane>>2, tg = lane&3;
  const int wm = (wid&1)*64, wn = (wid>>1)*32;

  float acc[4][4][4];
#pragma unroll
  for (int i=0;i<4;i++)
#pragma unroll
    for (int j=0;j<4;j++)
#pragma unroll
      for (int r=0;r<4;r++) acc[i][j][r]=0.f;

  auto loadA = [&](int kt, int st){
    int k0 = kt*16;
    float* dst = As + st*ASZ;
    if (AROW){
      for (int idx=tid; idx<512; idx+=256){
        int row=idx>>2, kq=idx&3; int m=m0+row, k=k0+kq*4;
        bool pred = (m < p.M) && (k+4 <= p.K);
        size_t base = 0;
        if (pred){
          if (AMODE==0) base = (size_t)m*p.lda;
          else if (AMODE==1){ int b=m/20, tt=m-b*20; base=((size_t)(b*120+tt))*2048; }
          else { int b=m/100, rm=m-b*100; int u=1+rm/20, tt=rm-(u-1)*20;
                 base=((size_t)(b*120+u*20+tt))*2048; }
        }
        cp16(dst + row*20+kq*4, pred ? (p.A+base+k) : p.A, pred);
      }
    } else {
      for (int idx=tid; idx<512; idx+=256){
        int kl=idx>>5, mq=idx&31; int k=k0+kl, m=m0+mq*4;
        bool pred = (k < p.K) && (m+4 <= p.M);
        cp16(dst + kl*136+mq*4, pred ? (p.A+(size_t)k*p.lda+m) : p.A, pred);
      }
    }
  };
  auto loadB = [&](int kt, int st){
    int k0 = kt*16;
    float* dst = Bs + st*BSZ;
    if (BROW){
      for (int idx=tid; idx<512; idx+=256){
        int row=idx>>2, kq=idx&3; int n=n0+row, k=k0+kq*4;
        bool pred = (n < p.N) && (k+4 <= p.K);
        cp16(dst + row*20+kq*4, pred ? (p.B+(size_t)n*p.ldb+k) : p.B, pred);
      }
    } else {
      for (int idx=tid; idx<512; idx+=256){
        int kl=idx>>5, nq=idx&31; int k=k0+kl, n=n0+nq*4;
        bool pred = (k < p.K) && (n+4 <= p.N);
        cp16(dst + kl*136+nq*4, pred ? (p.B+(size_t)k*p.ldb+n) : p.B, pred);
      }
    }
  };

  const int ntk = (p.K + 15) >> 4;
  loadA(0,0); loadB(0,0); CP_COMMIT();
  loadA(1,1); loadB(1,1); CP_COMMIT();   // kt>=ntk safely zero-fills

  for (int kt=0; kt<ntk; kt++){
    const int st = kt % 3;
    CP_WAIT1();
    __syncthreads();

    const float* Ast = As + st*ASZ;
    const float* Bst = Bs + st*BSZ;
#pragma unroll
    for (int kk=0; kk<16; kk+=8){
      float a[4][4];
#pragma unroll
      for (int i=0;i<4;i++){
        int mr = wm + i*16 + gr;
        if (AROW){
          a[i][0]=Ast[ mr   *20 + kk+tg  ];
          a[i][1]=Ast[(mr+8)*20 + kk+tg  ];
          a[i][2]=Ast[ mr   *20 + kk+tg+4];
          a[i][3]=Ast[(mr+8)*20 + kk+tg+4];
        } else {
          a[i][0]=Ast[(kk+tg  )*136 + mr  ];
          a[i][1]=Ast[(kk+tg  )*136 + mr+8];
          a[i][2]=Ast[(kk+tg+4)*136 + mr  ];
          a[i][3]=Ast[(kk+tg+4)*136 + mr+8];
        }
        if (ACVT){
#pragma unroll
          for (int q=0;q<4;q++) a[i][q] = to_tf32(a[i][q]);
        }
      }
      float b[4][2];
#pragma unroll
      for (int j=0;j<4;j++){
        int nc = wn + j*8 + gr;
        if (BROW){
          b[j][0]=Bst[nc*20 + kk+tg  ];
          b[j][1]=Bst[nc*20 + kk+tg+4];
        } else {
          b[j][0]=Bst[(kk+tg  )*136 + nc];
          b[j][1]=Bst[(kk+tg+4)*136 + nc];
        }
      }
#pragma unroll
      for (int i=0;i<4;i++)
#pragma unroll
        for (int j=0;j<4;j++) mma8(acc[i][j], a[i], b[j]);
    }
    // issue tile kt+2 into stage (kt+2)%3 (zero-fill past end keeps
    // group accounting in-order for CP_WAIT1)
    loadA(kt+2, (kt+2)%3); loadB(kt+2, (kt+2)%3);
    CP_COMMIT();
  }

  // ---- epilogue
#pragma unroll
  for (int i=0;i<4;i++){
#pragma unroll
    for (int r=0;r<4;r++){
      int m = m0 + wm + i*16 + gr + ((r>=2)?8:0);
      if (m >= p.M) continue;
      size_t crow;
      if (CMODE==0) crow = (size_t)m;
      else if (CMODE==1) crow = (size_t)m * 6;
      else { int b=m/100, rm=m-b*100; int u=1+rm/20, tt=rm-(u-1)*20;
             crow = ((size_t)(b*20+tt))*6 + u; }
#pragma unroll
      for (int j=0;j<4;j++){
        int n = n0 + wn + j*8 + tg*2 + (r&1);
        if (n >= p.N) continue;
        float v = acc[i][j][r];
        if (EPI==1){ v += p.bias1[n]; v = fmaxf(v, 0.f); }
        if (EPI==2){ v = to_tf32(v); }
        p.C[crow*(size_t)p.ldc + n] = v;
      }
    }
  }
}

// ---------------------------------------------------------------------------
// Persistent fused bidir RNN layer: block owns 32 rows, loops 20 steps.
// OUT written tf32-rounded (consumed only as GEMM A operands).
// ---------------------------------------------------------------------------
template<int HD>
__global__ __launch_bounds__(256) void rnnfuse_k(const float* __restrict__ XP,
    const float* __restrict__ Whh, const float* __restrict__ bih,
    const float* __restrict__ bhh, float* __restrict__ OUT, int M)
{
  constexpr int HP = HD+4;
  constexpr int BP = HD+8;
  constexpr int NJ = HD/64;
  extern __shared__ float sm[];
  float* hs  = sm;
  float* Bsm = sm + 32*HP;

  const int d  = blockIdx.z;
  const int r0 = blockIdx.x*32;
  const int tid = threadIdx.x, wid = tid>>5, lane = tid&31;
  const int gr = lane>>2, tg = lane&3;
  const int wn = wid*(HD/8);
  const float* Bp = Whh + (size_t)d*HD*HD;

  float bb[NJ][2];
#pragma unroll
  for (int j=0;j<NJ;j++){
    int n = wn + j*8 + tg*2;
    bb[j][0] = bih[d*HD+n]   + bhh[d*HD+n];
    bb[j][1] = bih[d*HD+n+1] + bhh[d*HD+n+1];
  }

  for (int s=0; s<20; s++){
    int t = d ? (19 - s) : s;
    float acc[2][NJ][4];
#pragma unroll
    for (int i=0;i<2;i++)
#pragma unroll
      for (int j=0;j<NJ;j++)
#pragma unroll
        for (int r=0;r<4;r++) acc[i][j][r]=0.f;

    if (s > 0){
      for (int k0=0; k0<HD; k0+=16){
        __syncthreads();
        for (int idx=tid; idx<HD*4; idx+=256){
          int nl=idx>>2, kq=idx&3;
          float4 v = *(const float4*)&Bp[(size_t)nl*HD + k0 + kq*4];
          Bsm[(kq*4+0)*BP + nl]=to_tf32(v.x);
          Bsm[(kq*4+1)*BP + nl]=to_tf32(v.y);
          Bsm[(kq*4+2)*BP + nl]=to_tf32(v.z);
          Bsm[(kq*4+3)*BP + nl]=to_tf32(v.w);
        }
        __syncthreads();
#pragma unroll
        for (int kk=0; kk<16; kk+=8){
          float a[2][4];
#pragma unroll
          for (int i=0;i<2;i++){
            int lr = i*16 + gr;
            a[i][0]=hs[ lr   *HP + k0+kk+tg  ];
            a[i][1]=hs[(lr+8)*HP + k0+kk+tg  ];
            a[i][2]=hs[ lr   *HP + k0+kk+tg+4];
            a[i][3]=hs[(lr+8)*HP + k0+kk+tg+4];
          }
          float b[NJ][2];
#pragma unroll
          for (int j=0;j<NJ;j++){
            int nc = wn + j*8 + gr;
            b[j][0]=Bsm[(kk+tg  )*BP + nc];
            b[j][1]=Bsm[(kk+tg+4)*BP + nc];
          }
#pragma unroll
          for (int i=0;i<2;i++)
#pragma unroll
            for (int j=0;j<NJ;j++) mma8(acc[i][j], a[i], b[j]);
        }
      }
    }
    __syncthreads();
#pragma unroll
    for (int i=0;i<2;i++)
#pragma unroll
      for (int r=0;r<4;r++){
        int lm = i*16 + gr + ((r>=2)?8:0);
        int m  = r0 + lm;
#pragma unroll
        for (int j=0;j<NJ;j++){
          int n = wn + j*8 + tg*2 + (r&1);
          if (m < M){
            size_t o = ((size_t)m*20 + t)*(size_t)(2*HD) + (size_t)d*HD + n;
            float v = to_tf32(tanhf(acc[i][j][r] + XP[o] + bb[j][r&1]));
            OUT[o] = v;
            hs[lm*HP + n] = v;
          } else {
            hs[lm*HP + n] = 0.f;
          }
        }
      }
  }
}

__global__ void chco_k(const float* bph, const float* bpo, const float* Wg1,
                       float* CHv, float* COv)
{
  __shared__ float sa[256], sc[256];
  int hl = threadIdx.x & 31, sl = threadIdx.x >> 5;
  int h = blockIdx.x*32 + hl;
  float a=0.f, c=0.f;
  for (int q=0; q<125; q++){
    int pp = sl*125 + q;
    a += bph[pp]*Wg1[(size_t)(4+pp)*512 + h];
    c += bpo[pp]*Wg1[(size_t)(1004+pp)*512 + h];
  }
  sa[threadIdx.x]=a; sc[threadIdx.x]=c;
  __syncthreads();
  if (sl==0){
    for (int s2=1;s2<8;s2++){ a+=sa[s2*32+hl]; c+=sc[s2*32+hl]; }
    CHv[h]=a; COv[h]=c;
  }
}

// mix1: slivers + A_HAT mix + bg1 + relu; output tf32-rounded (GEMM A operand)
__global__ void mix1_k(const float* __restrict__ Y, const float* __restrict__ Wg1,
                       const float* __restrict__ bg1, const float* __restrict__ bbox,
                       const float* __restrict__ oh, const float* __restrict__ CHv,
                       const float* __restrict__ COv, float* __restrict__ G1)
{
  int bt = blockIdx.x; int b = bt/20, t = bt - b*20;
  __shared__ float sb[24], so[50];
  int tid = threadIdx.x;
  if (tid < 24) sb[tid] = bbox[((size_t)(b*6 + (tid>>2))*20 + t)*4 + (tid&3)];
  if (tid >= 32 && tid < 82) {
    int q = tid-32;
    so[q] = oh[((size_t)(b*5 + q/10)*20 + t)*10 + (q - (q/10)*10)];
  }
  __syncthreads();
  int h = tid;
  size_t base = (size_t)bt * 6 * 512;
  float y0 = Y[base + h] + CHv[h];
#pragma unroll
  for (int i=0;i<4;i++) y0 += sb[i]*Wg1[(size_t)i*512 + h];
  float ys = 0.f, yu[5];
#pragma unroll
  for (int u=1; u<=5; u++){
    float v = Y[base + (size_t)u*512 + h] + COv[h];
#pragma unroll
    for (int i=0;i<4;i++) v += sb[u*4+i]*Wg1[(size_t)(2004+i)*512 + h];
#pragma unroll
    for (int j=0;j<10;j++) v += so[(u-1)*10+j]*Wg1[(size_t)(2008+j)*512 + h];
    yu[u-1]=v; ys += v;
  }
  const float R6 = 1.f/6.f, R12 = 0.28867513459481287f;
  float bg = bg1[h];
  G1[base + h] = to_tf32(fmaxf(R6*y0 + R12*ys + bg, 0.f));
#pragma unroll
  for (int u=1;u<=5;u++)
    G1[base + (size_t)u*512 + h] = to_tf32(fmaxf(R12*y0 + 0.5f*yu[u-1] + bg, 0.f));
}

// mix2: A_HAT mix + bg2 + relu -> SG (rounded), HN (rounded)
__global__ void mix2_k(const float* __restrict__ Z, const float* __restrict__ bg2,
                       float* __restrict__ SG, float* __restrict__ HN)
{
  int bt = blockIdx.x;
  int h = threadIdx.x;
  size_t base = (size_t)bt*6*512;
  float z0 = Z[base+h];
  float zs=0.f, zu[5];
#pragma unroll
  for (int u=1;u<=5;u++){ float v = Z[base+(size_t)u*512+h]; zu[u-1]=v; zs+=v; }
  const float R6 = 1.f/6.f, R12 = 0.28867513459481287f;
  float bg = bg2[h];
  float g0 = to_tf32(fmaxf(R6*z0 + R12*zs + bg, 0.f));
  SG[base+h]=g0;
  HN[(size_t)bt*512+h]=g0;
#pragma unroll
  for (int u=1;u<=5;u++)
    SG[base+(size_t)u*512+h] = to_tf32(fmaxf(R12*z0 + 0.5f*zu[u-1] + bg, 0.f));
}

__global__ void prefix_k(const int* num, int* off){
  if (threadIdx.x==0){
    int a=0;
    for (int b=0;b<256;b++){ off[b]=a; a+=num[b]; }
    off[256]=a;
  }
}

__global__ void gather_k(const float* __restrict__ SG, const int* __restrict__ num,
                         const int* __restrict__ off, float* __restrict__ ON)
{
  int bk = blockIdx.x; int b = bk/5, k = bk - b*5;
  if (k >= num[b]) return;
  int t = blockIdx.y;
  int r = off[b] + k;
  size_t ob  = ((size_t)r*20 + t)*1024;
  size_t sgb = ((size_t)(b*20+t))*6*512;
  int h = threadIdx.x;
  ON[ob + h]       = SG[sgb + h];
  ON[ob + 512 + h] = SG[sgb + (size_t)(k+1)*512 + h];
}

__global__ void head_k(const float* __restrict__ A1, const float* __restrict__ W2,
                       const float* __restrict__ b2, float* __restrict__ out, int nout)
{
  int r = blockIdx.x;
  __shared__ float cs[512];
  __shared__ float red[256];
  int tid = threadIdx.x;
  for (int j = tid; j < 512; j += 256){
    float s = 0.f;
    for (int t=0;t<20;t++) s += A1[((size_t)r*20 + t)*512 + j];
    cs[j] = s;
  }
  __syncthreads();
  for (int i=0;i<nout;i++){
    float v = cs[tid]*W2[(size_t)i*512+tid] + cs[tid+256]*W2[(size_t)i*512+tid+256];
    red[tid]=v; __syncthreads();
    for (int st=128; st>0; st>>=1){ if (tid<st) red[tid]+=red[tid+st]; __syncthreads(); }
    if (tid==0) out[(size_t)r*nout + i] = red[0] + 20.f*b2[i];
    __syncthreads();
  }
}

// ------------------------------- host side ---------------------------------
template<int AM,int BM2,int CM,int EP,int AC>
static inline void launch_f(const GemmP& p){
  constexpr int ASZ = (AM!=3) ? 128*20 : 16*136;
  constexpr int BSZ = (BM2==1) ? 128*20 : 16*136;
  constexpr int SMB = 3*(ASZ+BSZ)*4;
  cudaFuncSetAttribute(fgemm_k<AM,BM2,CM,EP,AC>,
                       cudaFuncAttributeMaxDynamicSharedMemorySize, SMB);
  dim3 g((unsigned)((p.N+127)/128), (unsigned)((p.M+127)/128), 1);
  fgemm_k<AM,BM2,CM,EP,AC><<<g,256,SMB>>>(p);
}

extern "C" void kernel_launch(void* const* d_in, const int* in_sizes, int n_in,
                              void* d_out, int out_size)
{
  const float* one_hot = (const float*)d_in[0];
  const float* bbox    = (const float*)d_in[1];
  const int*   numobj  = (const int*)  d_in[2];
  const float* rf      = (const float*)d_in[3];
  const float* Wph  = (const float*)d_in[4];
  const float* bph  = (const float*)d_in[5];
  const float* Wpo  = (const float*)d_in[6];
  const float* bpo  = (const float*)d_in[7];
  const float* Wg1  = (const float*)d_in[8];
  const float* bg1  = (const float*)d_in[9];
  const float* Wg2  = (const float*)d_in[10];
  const float* bg2  = (const float*)d_in[11];
  const float* sWih = (const float*)d_in[12];
  const float* sWhh = (const float*)d_in[13];
  const float* sbih = (const float*)d_in[14];
  const float* sbhh = (const float*)d_in[15];
  const float* aWih = (const float*)d_in[16];
  const float* aWhh = (const float*)d_in[17];
  const float* abih = (const float*)d_in[18];
  const float* abhh = (const float*)d_in[19];
  const float* chW1 = (const float*)d_in[20];
  const float* chb1 = (const float*)d_in[21];
  const float* chW2 = (const float*)d_in[22];
  const float* chb2 = (const float*)d_in[23];
  const float* coW1 = (const float*)d_in[24];
  const float* cob1 = (const float*)d_in[25];
  const float* coW2 = (const float*)d_in[26];
  const float* cob2 = (const float*)d_in[27];
  float* out = (float*)d_out;

  int Ntot = (out_size - 2560) / 12;
  if (Ntot < 0) Ntot = 0; if (Ntot > 1280) Ntot = 1280;

  float *MH,*MO,*CHv,*COv,*Y,*G1,*Z,*SG,*HN,*ON,*XPH,*HR0,*HR1,*XPO,*OR0,*OR1,*A1H,*A1O;
  float *Wphr,*Wpor,*Wg1r,*Wg2r,*sWihr,*aWihr,*chW1r,*coW1r;
  int *off;
  cudaGetSymbolAddress((void**)&MH,  g_MH);
  cudaGetSymbolAddress((void**)&MO,  g_MO);
  cudaGetSymbolAddress((void**)&CHv, g_CHv);
  cudaGetSymbolAddress((void**)&COv, g_COv);
  cudaGetSymbolAddress((void**)&Y,   g_Y);
  cudaGetSymbolAddress((void**)&G1,  g_G1);
  cudaGetSymbolAddress((void**)&Z,   g_Z);
  cudaGetSymbolAddress((void**)&SG,  g_SG);
  cudaGetSymbolAddress((void**)&HN,  g_HN);
  cudaGetSymbolAddress((void**)&ON,  g_ON);
  cudaGetSymbolAddress((void**)&XPH, g_XPH);
  cudaGetSymbolAddress((void**)&HR0, g_HR0);
  cudaGetSymbolAddress((void**)&HR1, g_HR1);
  cudaGetSymbolAddress((void**)&XPO, g_XPO);
  cudaGetSymbolAddress((void**)&OR0, g_OR0);
  cudaGetSymbolAddress((void**)&OR1, g_OR1);
  cudaGetSymbolAddress((void**)&A1H, g_A1H);
  cudaGetSymbolAddress((void**)&A1O, g_A1O);
  cudaGetSymbolAddress((void**)&off, g_off);
  cudaGetSymbolAddress((void**)&Wphr, g_Wphr);
  cudaGetSymbolAddress((void**)&Wpor, g_Wpor);
  cudaGetSymbolAddress((void**)&Wg1r, g_Wg1r);
  cudaGetSymbolAddress((void**)&Wg2r, g_Wg2r);
  cudaGetSymbolAddress((void**)&sWihr,g_sWihr);
  cudaGetSymbolAddress((void**)&aWihr,g_aWihr);
  cudaGetSymbolAddress((void**)&chW1r,g_chW1r);
  cudaGetSymbolAddress((void**)&coW1r,g_coW1r);

  const int SMEM512 = 32*(512+4)*4 + 16*(512+8)*4;  // 99,328 B
  const int SMEM256 = 32*(256+4)*4 + 16*(256+8)*4;  // 50,176 B
  cudaFuncSetAttribute(rnnfuse_k<512>, cudaFuncAttributeMaxDynamicSharedMemorySize, SMEM512);
  cudaFuncSetAttribute(rnnfuse_k<256>, cudaFuncAttributeMaxDynamicSharedMemorySize, SMEM256);

  // ---- pre-round weight operands (small buffers; rf stays raw, ACVT handles it)
  roundcopy_k<<<256,256>>>(Wph,  Wphr, 2048000);
  roundcopy_k<<<256,256>>>(Wpo,  Wpor, 2048000);
  roundcopy_k<<<256,256>>>(Wg1,  Wg1r, 1033216);
  roundcopy_k<<<64,256>>>(Wg2,  Wg2r, 262144);
  roundcopy_k<<<64,256>>>(sWih, sWihr,524288);
  roundcopy_k<<<256,256>>>(aWih, aWihr,2097152);
  roundcopy_k<<<64,256>>>(chW1, chW1r,262144);
  roundcopy_k<<<64,256>>>(coW1, coW1r,524288);

  // MH = Wph^T @ Wg1[4:1004] ; MO = Wpo^T @ Wg1[1004:2004]  (outputs rounded)
  { GemmP p{}; p.A=Wphr; p.lda=2048; p.B=Wg1r+4*512; p.ldb=512;
    p.C=MH; p.ldc=512; p.M=2048; p.N=512; p.K=1000; launch_f<3,0,0,2,0>(p); }
  { GemmP p{}; p.A=Wpor; p.lda=2048; p.B=Wg1r+1004*512; p.ldb=512;
    p.C=MO; p.ldc=512; p.M=2048; p.N=512; p.K=1000; launch_f<3,0,0,2,0>(p); }
  chco_k<<<16,256>>>(bph, bpo, Wg1, CHv, COv);

  // Y = rf @ M  (written [b,t,u,512]); rf raw -> ACVT=1
  { GemmP p{}; p.A=rf; p.B=MH; p.ldb=512;
    p.C=Y; p.ldc=512; p.M=5120; p.N=512; p.K=2048; launch_f<1,0,1,0,1>(p); }
  { GemmP p{}; p.A=rf; p.B=MO; p.ldb=512;
    p.C=Y; p.ldc=512; p.M=25600; p.N=512; p.K=2048; launch_f<2,0,2,0,1>(p); }
  mix1_k<<<5120,512>>>(Y, Wg1, bg1, bbox, one_hot, CHv, COv, G1);

  // Z = G1 @ Wg2 -> mix2 -> SG, HN
  { GemmP p{}; p.A=G1; p.lda=512; p.B=Wg2r; p.ldb=512;
    p.C=Z; p.ldc=512; p.M=30720; p.N=512; p.K=512; launch_f<0,0,0,0,0>(p); }
  mix2_k<<<5120,512>>>(Z, bg2, SG, HN);

  prefix_k<<<1,32>>>(numobj, off);
  gather_k<<<dim3(1280,20),512>>>(SG, numobj, off, ON);

  // human bidir RNN (hidden 256/dir)
  for (int l=0;l<2;l++){
    GemmP p{}; p.A = (l==0)?HN:HR0; p.lda=512;
    p.B = sWihr + (size_t)l*2*256*512; p.ldb=512;
    p.C = XPH; p.ldc=512; p.M=5120; p.N=512; p.K=512;
    launch_f<0,1,0,0,0>(p);
    float* HRl = (l==0)?HR0:HR1;
    rnnfuse_k<256><<<dim3(8,1,2),256,SMEM256>>>(
        XPH, sWhh + (size_t)l*2*256*256,
        sbih + (size_t)l*2*256, sbhh + (size_t)l*2*256, HRl, 256);
  }

  // object bidir RNN (hidden 512/dir)
  if (Ntot > 0) {
    int rb = (Ntot + 31)/32;
    for (int l=0;l<2;l++){
      GemmP p{}; p.A = (l==0)?ON:OR0; p.lda=1024;
      p.B = aWihr + (size_t)l*2*512*1024; p.ldb=1024;
      p.C = XPO; p.ldc=1024; p.M=Ntot*20; p.N=1024; p.K=1024;
      launch_f<0,1,0,0,0>(p);
      float* ORl = (l==0)?OR0:OR1;
      rnnfuse_k<512><<<dim3(rb,1,2),256,SMEM512>>>(
          XPO, aWhh + (size_t)l*2*512*512,
          abih + (size_t)l*2*512, abhh + (size_t)l*2*512, ORl, Ntot);
    }
  }

  // heads
  { GemmP p{}; p.A=HR1; p.lda=512; p.B=chW1r; p.ldb=512;
    p.C=A1H; p.ldc=512; p.M=5120; p.N=512; p.K=512;
    p.bias1=chb1; launch_f<0,1,0,1,0>(p); }
  head_k<<<256,256>>>(A1H, chW2, chb2, out, 10);

  if (Ntot > 0) {
    GemmP p{}; p.A=OR1; p.lda=1024; p.B=coW1r; p.ldb=1024;
    p.C=A1O; p.ldc=512; p.M=Ntot*20; p.N=512; p.K=1024;
    p.bias1=cob1; launch_f<0,1,0,1,0>(p);
    head_k<<<Ntot,256>>>(A1O, coW2, cob2, out + 2560, 12);
  }
}

// round 12
// speedup vs baseline: 1.0174x; 1.0174x over previous
#include <cuda_runtime.h>
#include <cstdint>
#include <math.h>

// B=256 T=20 NOBJ=5 D=2048 P=1000 IN=2018 H=512

// ------------------------- device scratch -------------------------
__device__ float g_MH [2048*512];
__device__ float g_MO [2048*512];
__device__ float g_CHv[512];
__device__ float g_COv[512];
__device__ float g_Y  [30720*512];
__device__ float g_G1 [30720*512];
__device__ float g_Z  [30720*512];
__device__ float g_SG [30720*512];
__device__ float g_HN [5120*512];
__device__ float g_ON [25600*1024];
__device__ float g_XPH[5120*512];
__device__ float g_HR0[5120*512];
__device__ float g_HR1[5120*512];
__device__ float g_XPO[25600*1024];
__device__ float g_OR0[25600*1024];
__device__ float g_OR1[25600*1024];
__device__ float g_A1H[5120*512];
__device__ float g_A1O[25600*512];
__device__ int   g_off[257];
// pre-rounded (tf32-in-fp32) weight copies (small buffers only)
__device__ float g_Wphr [2048000];
__device__ float g_Wpor [2048000];
__device__ float g_Wg1r [1033216];
__device__ float g_Wg2r [262144];
__device__ float g_sWihr[524288];
__device__ float g_aWihr[2097152];
__device__ float g_chW1r[262144];
__device__ float g_coW1r[524288];

struct GemmP {
  const float* A; const float* B; float* C;
  int M, N, K;
  int lda, ldb, ldc;
  const float* bias1;
};

__device__ __forceinline__ float to_tf32(float x){
  float r; asm("cvt.rna.tf32.f32 %0, %1;" : "=f"(r) : "f"(x)); return r;
}

__device__ __forceinline__ void mma8(float (&c)[4], const float (&a)[4], const float (&b)[2]){
  asm volatile(
    "mma.sync.aligned.m16n8k8.row.col.f32.tf32.tf32.f32 "
    "{%0,%1,%2,%3}, {%4,%5,%6,%7}, {%8,%9}, {%0,%1,%2,%3};\n"
    : "+f"(c[0]), "+f"(c[1]), "+f"(c[2]), "+f"(c[3])
    : "r"(__float_as_uint(a[0])), "r"(__float_as_uint(a[1])),
      "r"(__float_as_uint(a[2])), "r"(__float_as_uint(a[3])),
      "r"(__float_as_uint(b[0])), "r"(__float_as_uint(b[1])));
}

__device__ __forceinline__ void cp16(float* smem_ptr, const float* gmem, bool pred){
  unsigned int s = (unsigned int)__cvta_generic_to_shared(smem_ptr);
  int sz = pred ? 16 : 0;
  asm volatile("cp.async.cg.shared.global [%0], [%1], 16, %2;\n"
               :: "r"(s), "l"(gmem), "r"(sz));
}
#define CP_COMMIT() asm volatile("cp.async.commit_group;\n")
#define CP_WAIT2()  asm volatile("cp.async.wait_group 2;\n")

// grid-stride tf32 rounding copy (n % 4 == 0)
__global__ void roundcopy_k(const float* __restrict__ src, float* __restrict__ dst, int n){
  int i = (blockIdx.x*blockDim.x + threadIdx.x)*4;
  int stride = gridDim.x*blockDim.x*4;
  for (; i+3 < n; i += stride){
    float4 v = *(const float4*)(src+i);
    float4 w; w.x=to_tf32(v.x); w.y=to_tf32(v.y); w.z=to_tf32(v.z); w.w=to_tf32(v.w);
    *(float4*)(dst+i) = w;
  }
}

// ---------------------------------------------------------------------------
// 4-stage cp.async tf32 GEMM (prefetch distance 3). BM=128, BN=128, BK=16;
// 8 warps (2m x 4n), warp tile 64x32.
//  AMODE: 0 A[m*lda+k], 1 human-RF rows, 2 obj-RF rows, 3 A[k*lda+m]
//  BMODE: 0 B[k*ldb+n], 1 B[n*ldb+k]
//  CMODE: 0 crow=m, 1 crow=m*6, 2 obj row map
//  EPI:   0 none, 1 bias+relu, 2 round output to tf32
//  ACVT:  1 -> convert A-frags to tf32 in-register (A not pre-rounded)
//  B (and A when ACVT=0) must be pre-rounded tf32-in-fp32.
//  Row-major tile: [128][20] ; K-major tile: [16][136]. One barrier/iter.
// ---------------------------------------------------------------------------
template<int AMODE,int BMODE,int CMODE,int EPI,int ACVT>
__global__ __launch_bounds__(256,2) void fgemm_k(GemmP p)
{
  constexpr bool AROW = (AMODE != 3);
  constexpr bool BROW = (BMODE == 1);
  constexpr int ASZ = AROW ? 128*20 : 16*136;
  constexpr int BSZ = BROW ? 128*20 : 16*136;
  extern __shared__ float dsm[];
  float* As = dsm;              // [4][ASZ]
  float* Bs = dsm + 4*ASZ;      // [4][BSZ]

  const int m0 = blockIdx.y * 128;
  const int n0 = blockIdx.x * 128;
  const int tid = threadIdx.x, wid = tid>>5, lane = tid&31;
  const int gr = lane>>2, tg = lane&3;
  const int wm = (wid&1)*64, wn = (wid>>1)*32;

  float acc[4][4][4];
#pragma unroll
  for (int i=0;i<4;i++)
#pragma unroll
    for (int j=0;j<4;j++)
#pragma unroll
      for (int r=0;r<4;r++) acc[i][j][r]=0.f;

  auto loadA = [&](int kt, int st){
    int k0 = kt*16;
    float* dst = As + st*ASZ;
    if (AROW){
      for (int idx=tid; idx<512; idx+=256){
        int row=idx>>2, kq=idx&3; int m=m0+row, k=k0+kq*4;
        bool pred = (m < p.M) && (k+4 <= p.K);
        size_t base = 0;
        if (pred){
          if (AMODE==0) base = (size_t)m*p.lda;
          else if (AMODE==1){ int b=m/20, tt=m-b*20; base=((size_t)(b*120+tt))*2048; }
          else { int b=m/100, rm=m-b*100; int u=1+rm/20, tt=rm-(u-1)*20;
                 base=((size_t)(b*120+u*20+tt))*2048; }
        }
        cp16(dst + row*20+kq*4, pred ? (p.A+base+k) : p.A, pred);
      }
    } else {
      for (int idx=tid; idx<512; idx+=256){
        int kl=idx>>5, mq=idx&31; int k=k0+kl, m=m0+mq*4;
        bool pred = (k < p.K) && (m+4 <= p.M);
        cp16(dst + kl*136+mq*4, pred ? (p.A+(size_t)k*p.lda+m) : p.A, pred);
      }
    }
  };
  auto loadB = [&](int kt, int st){
    int k0 = kt*16;
    float* dst = Bs + st*BSZ;
    if (BROW){
      for (int idx=tid; idx<512; idx+=256){
        int row=idx>>2, kq=idx&3; int n=n0+row, k=k0+kq*4;
        bool pred = (n < p.N) && (k+4 <= p.K);
        cp16(dst + row*20+kq*4, pred ? (p.B+(size_t)n*p.ldb+k) : p.B, pred);
      }
    } else {
      for (int idx=tid; idx<512; idx+=256){
        int kl=idx>>5, nq=idx&31; int k=k0+kl, n=n0+nq*4;
        bool pred = (k < p.K) && (n+4 <= p.N);
        cp16(dst + kl*136+nq*4, pred ? (p.B+(size_t)k*p.ldb+n) : p.B, pred);
      }
    }
  };

  const int ntk = (p.K + 15) >> 4;
  loadA(0,0); loadB(0,0); CP_COMMIT();
  loadA(1,1); loadB(1,1); CP_COMMIT();   // kt>=ntk safely zero-fills
  loadA(2,2); loadB(2,2); CP_COMMIT();

  for (int kt=0; kt<ntk; kt++){
    const int st = kt & 3;
    CP_WAIT2();
    __syncthreads();

    const float* Ast = As + st*ASZ;
    const float* Bst = Bs + st*BSZ;
#pragma unroll
    for (int kk=0; kk<16; kk+=8){
      float a[4][4];
#pragma unroll
      for (int i=0;i<4;i++){
        int mr = wm + i*16 + gr;
        if (AROW){
          a[i][0]=Ast[ mr   *20 + kk+tg  ];
          a[i][1]=Ast[(mr+8)*20 + kk+tg  ];
          a[i][2]=Ast[ mr   *20 + kk+tg+4];
          a[i][3]=Ast[(mr+8)*20 + kk+tg+4];
        } else {
          a[i][0]=Ast[(kk+tg  )*136 + mr  ];
          a[i][1]=Ast[(kk+tg  )*136 + mr+8];
          a[i][2]=Ast[(kk+tg+4)*136 + mr  ];
          a[i][3]=Ast[(kk+tg+4)*136 + mr+8];
        }
        if (ACVT){
#pragma unroll
          for (int q=0;q<4;q++) a[i][q] = to_tf32(a[i][q]);
        }
      }
      float b[4][2];
#pragma unroll
      for (int j=0;j<4;j++){
        int nc = wn + j*8 + gr;
        if (BROW){
          b[j][0]=Bst[nc*20 + kk+tg  ];
          b[j][1]=Bst[nc*20 + kk+tg+4];
        } else {
          b[j][0]=Bst[(kk+tg  )*136 + nc];
          b[j][1]=Bst[(kk+tg+4)*136 + nc];
        }
      }
#pragma unroll
      for (int i=0;i<4;i++)
#pragma unroll
        for (int j=0;j<4;j++) mma8(acc[i][j], a[i], b[j]);
    }
    // issue tile kt+3 into stage (kt+3)&3 = the stage consumed at iter kt-1;
    // the iter-kt barrier above retired all its readers. Zero-fill past end
    // keeps group accounting in-order for CP_WAIT2.
    loadA(kt+3, (kt+3)&3); loadB(kt+3, (kt+3)&3);
    CP_COMMIT();
  }

  // ---- epilogue
#pragma unroll
  for (int i=0;i<4;i++){
#pragma unroll
    for (int r=0;r<4;r++){
      int m = m0 + wm + i*16 + gr + ((r>=2)?8:0);
      if (m >= p.M) continue;
      size_t crow;
      if (CMODE==0) crow = (size_t)m;
      else if (CMODE==1) crow = (size_t)m * 6;
      else { int b=m/100, rm=m-b*100; int u=1+rm/20, tt=rm-(u-1)*20;
             crow = ((size_t)(b*20+tt))*6 + u; }
#pragma unroll
      for (int j=0;j<4;j++){
        int n = n0 + wn + j*8 + tg*2 + (r&1);
        if (n >= p.N) continue;
        float v = acc[i][j][r];
        if (EPI==1){ v += p.bias1[n]; v = fmaxf(v, 0.f); }
        if (EPI==2){ v = to_tf32(v); }
        p.C[crow*(size_t)p.ldc + n] = v;
      }
    }
  }
}

// ---------------------------------------------------------------------------
// Persistent fused bidir RNN layer: block owns 32 rows, loops 20 steps.
// OUT written tf32-rounded (consumed only as GEMM A operands).
// ---------------------------------------------------------------------------
template<int HD>
__global__ __launch_bounds__(256) void rnnfuse_k(const float* __restrict__ XP,
    const float* __restrict__ Whh, const float* __restrict__ bih,
    const float* __restrict__ bhh, float* __restrict__ OUT, int M)
{
  constexpr int HP = HD+4;
  constexpr int BP = HD+8;
  constexpr int NJ = HD/64;
  extern __shared__ float sm[];
  float* hs  = sm;
  float* Bsm = sm + 32*HP;

  const int d  = blockIdx.z;
  const int r0 = blockIdx.x*32;
  const int tid = threadIdx.x, wid = tid>>5, lane = tid&31;
  const int gr = lane>>2, tg = lane&3;
  const int wn = wid*(HD/8);
  const float* Bp = Whh + (size_t)d*HD*HD;

  float bb[NJ][2];
#pragma unroll
  for (int j=0;j<NJ;j++){
    int n = wn + j*8 + tg*2;
    bb[j][0] = bih[d*HD+n]   + bhh[d*HD+n];
    bb[j][1] = bih[d*HD+n+1] + bhh[d*HD+n+1];
  }

  for (int s=0; s<20; s++){
    int t = d ? (19 - s) : s;
    float acc[2][NJ][4];
#pragma unroll
    for (int i=0;i<2;i++)
#pragma unroll
      for (int j=0;j<NJ;j++)
#pragma unroll
        for (int r=0;r<4;r++) acc[i][j][r]=0.f;

    if (s > 0){
      for (int k0=0; k0<HD; k0+=16){
        __syncthreads();
        for (int idx=tid; idx<HD*4; idx+=256){
          int nl=idx>>2, kq=idx&3;
          float4 v = *(const float4*)&Bp[(size_t)nl*HD + k0 + kq*4];
          Bsm[(kq*4+0)*BP + nl]=to_tf32(v.x);
          Bsm[(kq*4+1)*BP + nl]=to_tf32(v.y);
          Bsm[(kq*4+2)*BP + nl]=to_tf32(v.z);
          Bsm[(kq*4+3)*BP + nl]=to_tf32(v.w);
        }
        __syncthreads();
#pragma unroll
        for (int kk=0; kk<16; kk+=8){
          float a[2][4];
#pragma unroll
          for (int i=0;i<2;i++){
            int lr = i*16 + gr;
            a[i][0]=hs[ lr   *HP + k0+kk+tg  ];
            a[i][1]=hs[(lr+8)*HP + k0+kk+tg  ];
            a[i][2]=hs[ lr   *HP + k0+kk+tg+4];
            a[i][3]=hs[(lr+8)*HP + k0+kk+tg+4];
          }
          float b[NJ][2];
#pragma unroll
          for (int j=0;j<NJ;j++){
            int nc = wn + j*8 + gr;
            b[j][0]=Bsm[(kk+tg  )*BP + nc];
            b[j][1]=Bsm[(kk+tg+4)*BP + nc];
          }
#pragma unroll
          for (int i=0;i<2;i++)
#pragma unroll
            for (int j=0;j<NJ;j++) mma8(acc[i][j], a[i], b[j]);
        }
      }
    }
    __syncthreads();
#pragma unroll
    for (int i=0;i<2;i++)
#pragma unroll
      for (int r=0;r<4;r++){
        int lm = i*16 + gr + ((r>=2)?8:0);
        int m  = r0 + lm;
#pragma unroll
        for (int j=0;j<NJ;j++){
          int n = wn + j*8 + tg*2 + (r&1);
          if (m < M){
            size_t o = ((size_t)m*20 + t)*(size_t)(2*HD) + (size_t)d*HD + n;
            float v = to_tf32(tanhf(acc[i][j][r] + XP[o] + bb[j][r&1]));
            OUT[o] = v;
            hs[lm*HP + n] = v;
          } else {
            hs[lm*HP + n] = 0.f;
          }
        }
      }
  }
}

__global__ void chco_k(const float* bph, const float* bpo, const float* Wg1,
                       float* CHv, float* COv)
{
  __shared__ float sa[256], sc[256];
  int hl = threadIdx.x & 31, sl = threadIdx.x >> 5;
  int h = blockIdx.x*32 + hl;
  float a=0.f, c=0.f;
  for (int q=0; q<125; q++){
    int pp = sl*125 + q;
    a += bph[pp]*Wg1[(size_t)(4+pp)*512 + h];
    c += bpo[pp]*Wg1[(size_t)(1004+pp)*512 + h];
  }
  sa[threadIdx.x]=a; sc[threadIdx.x]=c;
  __syncthreads();
  if (sl==0){
    for (int s2=1;s2<8;s2++){ a+=sa[s2*32+hl]; c+=sc[s2*32+hl]; }
    CHv[h]=a; COv[h]=c;
  }
}

// mix1: slivers + A_HAT mix + bg1 + relu; output tf32-rounded (GEMM A operand)
__global__ void mix1_k(const float* __restrict__ Y, const float* __restrict__ Wg1,
                       const float* __restrict__ bg1, const float* __restrict__ bbox,
                       const float* __restrict__ oh, const float* __restrict__ CHv,
                       const float* __restrict__ COv, float* __restrict__ G1)
{
  int bt = blockIdx.x; int b = bt/20, t = bt - b*20;
  __shared__ float sb[24], so[50];
  int tid = threadIdx.x;
  if (tid < 24) sb[tid] = bbox[((size_t)(b*6 + (tid>>2))*20 + t)*4 + (tid&3)];
  if (tid >= 32 && tid < 82) {
    int q = tid-32;
    so[q] = oh[((size_t)(b*5 + q/10)*20 + t)*10 + (q - (q/10)*10)];
  }
  __syncthreads();
  int h = tid;
  size_t base = (size_t)bt * 6 * 512;
  float y0 = Y[base + h] + CHv[h];
#pragma unroll
  for (int i=0;i<4;i++) y0 += sb[i]*Wg1[(size_t)i*512 + h];
  float ys = 0.f, yu[5];
#pragma unroll
  for (int u=1; u<=5; u++){
    float v = Y[base + (size_t)u*512 + h] + COv[h];
#pragma unroll
    for (int i=0;i<4;i++) v += sb[u*4+i]*Wg1[(size_t)(2004+i)*512 + h];
#pragma unroll
    for (int j=0;j<10;j++) v += so[(u-1)*10+j]*Wg1[(size_t)(2008+j)*512 + h];
    yu[u-1]=v; ys += v;
  }
  const float R6 = 1.f/6.f, R12 = 0.28867513459481287f;
  float bg = bg1[h];
  G1[base + h] = to_tf32(fmaxf(R6*y0 + R12*ys + bg, 0.f));
#pragma unroll
  for (int u=1;u<=5;u++)
    G1[base + (size_t)u*512 + h] = to_tf32(fmaxf(R12*y0 + 0.5f*yu[u-1] + bg, 0.f));
}

// mix2: A_HAT mix + bg2 + relu -> SG (rounded), HN (rounded)
__global__ void mix2_k(const float* __restrict__ Z, const float* __restrict__ bg2,
                       float* __restrict__ SG, float* __restrict__ HN)
{
  int bt = blockIdx.x;
  int h = threadIdx.x;
  size_t base = (size_t)bt*6*512;
  float z0 = Z[base+h];
  float zs=0.f, zu[5];
#pragma unroll
  for (int u=1;u<=5;u++){ float v = Z[base+(size_t)u*512+h]; zu[u-1]=v; zs+=v; }
  const float R6 = 1.f/6.f, R12 = 0.28867513459481287f;
  float bg = bg2[h];
  float g0 = to_tf32(fmaxf(R6*z0 + R12*zs + bg, 0.f));
  SG[base+h]=g0;
  HN[(size_t)bt*512+h]=g0;
#pragma unroll
  for (int u=1;u<=5;u++)
    SG[base+(size_t)u*512+h] = to_tf32(fmaxf(R12*z0 + 0.5f*zu[u-1] + bg, 0.f));
}

__global__ void prefix_k(const int* num, int* off){
  if (threadIdx.x==0){
    int a=0;
    for (int b=0;b<256;b++){ off[b]=a; a+=num[b]; }
    off[256]=a;
  }
}

__global__ void gather_k(const float* __restrict__ SG, const int* __restrict__ num,
                         const int* __restrict__ off, float* __restrict__ ON)
{
  int bk = blockIdx.x; int b = bk/5, k = bk - b*5;
  if (k >= num[b]) return;
  int t = blockIdx.y;
  int r = off[b] + k;
  size_t ob  = ((size_t)r*20 + t)*1024;
  size_t sgb = ((size_t)(b*20+t))*6*512;
  int h = threadIdx.x;
  ON[ob + h]       = SG[sgb + h];
  ON[ob + 512 + h] = SG[sgb + (size_t)(k+1)*512 + h];
}

__global__ void head_k(const float* __restrict__ A1, const float* __restrict__ W2,
                       const float* __restrict__ b2, float* __restrict__ out, int nout)
{
  int r = blockIdx.x;
  __shared__ float cs[512];
  __shared__ float red[256];
  int tid = threadIdx.x;
  for (int j = tid; j < 512; j += 256){
    float s = 0.f;
    for (int t=0;t<20;t++) s += A1[((size_t)r*20 + t)*512 + j];
    cs[j] = s;
  }
  __syncthreads();
  for (int i=0;i<nout;i++){
    float v = cs[tid]*W2[(size_t)i*512+tid] + cs[tid+256]*W2[(size_t)i*512+tid+256];
    red[tid]=v; __syncthreads();
    for (int st=128; st>0; st>>=1){ if (tid<st) red[tid]+=red[tid+st]; __syncthreads(); }
    if (tid==0) out[(size_t)r*nout + i] = red[0] + 20.f*b2[i];
    __syncthreads();
  }
}

// ------------------------------- host side ---------------------------------
template<int AM,int BM2,int CM,int EP,int AC>
static inline void launch_f(const GemmP& p){
  constexpr int ASZ = (AM!=3) ? 128*20 : 16*136;
  constexpr int BSZ = (BM2==1) ? 128*20 : 16*136;
  constexpr int SMB = 4*(ASZ+BSZ)*4;
  cudaFuncSetAttribute(fgemm_k<AM,BM2,CM,EP,AC>,
                       cudaFuncAttributeMaxDynamicSharedMemorySize, SMB);
  dim3 g((unsigned)((p.N+127)/128), (unsigned)((p.M+127)/128), 1);
  fgemm_k<AM,BM2,CM,EP,AC><<<g,256,SMB>>>(p);
}

extern "C" void kernel_launch(void* const* d_in, const int* in_sizes, int n_in,
                              void* d_out, int out_size)
{
  const float* one_hot = (const float*)d_in[0];
  const float* bbox    = (const float*)d_in[1];
  const int*   numobj  = (const int*)  d_in[2];
  const float* rf      = (const float*)d_in[3];
  const float* Wph  = (const float*)d_in[4];
  const float* bph  = (const float*)d_in[5];
  const float* Wpo  = (const float*)d_in[6];
  const float* bpo  = (const float*)d_in[7];
  const float* Wg1  = (const float*)d_in[8];
  const float* bg1  = (const float*)d_in[9];
  const float* Wg2  = (const float*)d_in[10];
  const float* bg2  = (const float*)d_in[11];
  const float* sWih = (const float*)d_in[12];
  const float* sWhh = (const float*)d_in[13];
  const float* sbih = (const float*)d_in[14];
  const float* sbhh = (const float*)d_in[15];
  const float* aWih = (const float*)d_in[16];
  const float* aWhh = (const float*)d_in[17];
  const float* abih = (const float*)d_in[18];
  const float* abhh = (const float*)d_in[19];
  const float* chW1 = (const float*)d_in[20];
  const float* chb1 = (const float*)d_in[21];
  const float* chW2 = (const float*)d_in[22];
  const float* chb2 = (const float*)d_in[23];
  const float* coW1 = (const float*)d_in[24];
  const float* cob1 = (const float*)d_in[25];
  const float* coW2 = (const float*)d_in[26];
  const float* cob2 = (const float*)d_in[27];
  float* out = (float*)d_out;

  int Ntot = (out_size - 2560) / 12;
  if (Ntot < 0) Ntot = 0; if (Ntot > 1280) Ntot = 1280;

  float *MH,*MO,*CHv,*COv,*Y,*G1,*Z,*SG,*HN,*ON,*XPH,*HR0,*HR1,*XPO,*OR0,*OR1,*A1H,*A1O;
  float *Wphr,*Wpor,*Wg1r,*Wg2r,*sWihr,*aWihr,*chW1r,*coW1r;
  int *off;
  cudaGetSymbolAddress((void**)&MH,  g_MH);
  cudaGetSymbolAddress((void**)&MO,  g_MO);
  cudaGetSymbolAddress((void**)&CHv, g_CHv);
  cudaGetSymbolAddress((void**)&COv, g_COv);
  cudaGetSymbolAddress((void**)&Y,   g_Y);
  cudaGetSymbolAddress((void**)&G1,  g_G1);
  cudaGetSymbolAddress((void**)&Z,   g_Z);
  cudaGetSymbolAddress((void**)&SG,  g_SG);
  cudaGetSymbolAddress((void**)&HN,  g_HN);
  cudaGetSymbolAddress((void**)&ON,  g_ON);
  cudaGetSymbolAddress((void**)&XPH, g_XPH);
  cudaGetSymbolAddress((void**)&HR0, g_HR0);
  cudaGetSymbolAddress((void**)&HR1, g_HR1);
  cudaGetSymbolAddress((void**)&XPO, g_XPO);
  cudaGetSymbolAddress((void**)&OR0, g_OR0);
  cudaGetSymbolAddress((void**)&OR1, g_OR1);
  cudaGetSymbolAddress((void**)&A1H, g_A1H);
  cudaGetSymbolAddress((void**)&A1O, g_A1O);
  cudaGetSymbolAddress((void**)&off, g_off);
  cudaGetSymbolAddress((void**)&Wphr, g_Wphr);
  cudaGetSymbolAddress((void**)&Wpor, g_Wpor);
  cudaGetSymbolAddress((void**)&Wg1r, g_Wg1r);
  cudaGetSymbolAddress((void**)&Wg2r, g_Wg2r);
  cudaGetSymbolAddress((void**)&sWihr,g_sWihr);
  cudaGetSymbolAddress((void**)&aWihr,g_aWihr);
  cudaGetSymbolAddress((void**)&chW1r,g_chW1r);
  cudaGetSymbolAddress((void**)&coW1r,g_coW1r);

  const int SMEM512 = 32*(512+4)*4 + 16*(512+8)*4;  // 99,328 B
  const int SMEM256 = 32*(256+4)*4 + 16*(256+8)*4;  // 50,176 B
  cudaFuncSetAttribute(rnnfuse_k<512>, cudaFuncAttributeMaxDynamicSharedMemorySize, SMEM512);
  cudaFuncSetAttribute(rnnfuse_k<256>, cudaFuncAttributeMaxDynamicSharedMemorySize, SMEM256);

  // ---- pre-round weight operands (small buffers; rf stays raw, ACVT handles it)
  roundcopy_k<<<256,256>>>(Wph,  Wphr, 2048000);
  roundcopy_k<<<256,256>>>(Wpo,  Wpor, 2048000);
  roundcopy_k<<<256,256>>>(Wg1,  Wg1r, 1033216);
  roundcopy_k<<<64,256>>>(Wg2,  Wg2r, 262144);
  roundcopy_k<<<64,256>>>(sWih, sWihr,524288);
  roundcopy_k<<<256,256>>>(aWih, aWihr,2097152);
  roundcopy_k<<<64,256>>>(chW1, chW1r,262144);
  roundcopy_k<<<64,256>>>(coW1, coW1r,524288);

  // MH = Wph^T @ Wg1[4:1004] ; MO = Wpo^T @ Wg1[1004:2004]  (outputs rounded)
  { GemmP p{}; p.A=Wphr; p.lda=2048; p.B=Wg1r+4*512; p.ldb=512;
    p.C=MH; p.ldc=512; p.M=2048; p.N=512; p.K=1000; launch_f<3,0,0,2,0>(p); }
  { GemmP p{}; p.A=Wpor; p.lda=2048; p.B=Wg1r+1004*512; p.ldb=512;
    p.C=MO; p.ldc=512; p.M=2048; p.N=512; p.K=1000; launch_f<3,0,0,2,0>(p); }
  chco_k<<<16,256>>>(bph, bpo, Wg1, CHv, COv);

  // Y = rf @ M  (written [b,t,u,512]); rf raw -> ACVT=1
  { GemmP p{}; p.A=rf; p.B=MH; p.ldb=512;
    p.C=Y; p.ldc=512; p.M=5120; p.N=512; p.K=2048; launch_f<1,0,1,0,1>(p); }
  { GemmP p{}; p.A=rf; p.B=MO; p.ldb=512;
    p.C=Y; p.ldc=512; p.M=25600; p.N=512; p.K=2048; launch_f<2,0,2,0,1>(p); }
  mix1_k<<<5120,512>>>(Y, Wg1, bg1, bbox, one_hot, CHv, COv, G1);

  // Z = G1 @ Wg2 -> mix2 -> SG, HN
  { GemmP p{}; p.A=G1; p.lda=512; p.B=Wg2r; p.ldb=512;
    p.C=Z; p.ldc=512; p.M=30720; p.N=512; p.K=512; launch_f<0,0,0,0,0>(p); }
  mix2_k<<<5120,512>>>(Z, bg2, SG, HN);

  prefix_k<<<1,32>>>(numobj, off);
  gather_k<<<dim3(1280,20),512>>>(SG, numobj, off, ON);

  // human bidir RNN (hidden 256/dir)
  for (int l=0;l<2;l++){
    GemmP p{}; p.A = (l==0)?HN:HR0; p.lda=512;
    p.B = sWihr + (size_t)l*2*256*512; p.ldb=512;
    p.C = XPH; p.ldc=512; p.M=5120; p.N=512; p.K=512;
    launch_f<0,1,0,0,0>(p);
    float* HRl = (l==0)?HR0:HR1;
    rnnfuse_k<256><<<dim3(8,1,2),256,SMEM256>>>(
        XPH, sWhh + (size_t)l*2*256*256,
        sbih + (size_t)l*2*256, sbhh + (size_t)l*2*256, HRl, 256);
  }

  // object bidir RNN (hidden 512/dir)
  if (Ntot > 0) {
    int rb = (Ntot + 31)/32;
    for (int l=0;l<2;l++){
      GemmP p{}; p.A = (l==0)?ON:OR0; p.lda=1024;
      p.B = aWihr + (size_t)l*2*512*1024; p.ldb=1024;
      p.C = XPO; p.ldc=1024; p.M=Ntot*20; p.N=1024; p.K=1024;
      launch_f<0,1,0,0,0>(p);
      float* ORl = (l==0)?OR0:OR1;
      rnnfuse_k<512><<<dim3(rb,1,2),256,SMEM512>>>(
          XPO, aWhh + (size_t)l*2*512*512,
          abih + (size_t)l*2*512, abhh + (size_t)l*2*512, ORl, Ntot);
    }
  }

  // heads
  { GemmP p{}; p.A=HR1; p.lda=512; p.B=chW1r; p.ldb=512;
    p.C=A1H; p.ldc=512; p.M=5120; p.N=512; p.K=512;
    p.bias1=chb1; launch_f<0,1,0,1,0>(p); }
  head_k<<<256,256>>>(A1H, chW2, chb2, out, 10);

  if (Ntot > 0) {
    GemmP p{}; p.A=OR1; p.lda=1024; p.B=coW1r; p.ldb=1024;
    p.C=A1O; p.ldc=512; p.M=Ntot*20; p.N=512; p.K=1024;
    p.bias1=cob1; launch_f<0,1,0,1,0>(p);
    head_k<<<Ntot,256>>>(A1O, coW2, cob2, out + 2560, 12);
  }
}

// round 14
// speedup vs baseline: 1.0379x; 1.0202x over previous
#include <cuda_runtime.h>
#include <cstdint>
#include <math.h>

// B=256 T=20 NOBJ=5 D=2048 P=1000 IN=2018 H=512

// ------------------------- device scratch -------------------------
__device__ float g_MH [2048*512];
__device__ float g_MO [2048*512];
__device__ float g_CHv[512];
__device__ float g_COv[512];
__device__ float g_Y  [30720*512];
__device__ float g_G1 [30720*512];
__device__ float g_Z  [30720*512];
__device__ float g_SG [30720*512];
__device__ float g_HN [5120*512];
__device__ float g_ON [25600*1024];
__device__ float g_XPH[5120*512];
__device__ float g_HR0[5120*512];
__device__ float g_HR1[5120*512];
__device__ float g_XPO[25600*1024];
__device__ float g_OR0[25600*1024];
__device__ float g_OR1[25600*1024];
__device__ float g_A1H[5120*512];
__device__ float g_A1O[25600*512];
__device__ int   g_off[257];
// pre-rounded (tf32-in-fp32) weight copies
__device__ float g_Wphr [2048000];
__device__ float g_Wpor [2048000];
__device__ float g_Wg1r [1033216];
__device__ float g_Wg2r [262144];
__device__ float g_sWihr[524288];
__device__ float g_aWihr[2097152];
__device__ float g_chW1r[262144];
__device__ float g_coW1r[524288];

struct GemmP {
  const float* A; const float* B; float* C;
  int M, N, K;
  int lda, ldb, ldc;
  const float* bias1;
};

__device__ __forceinline__ float to_tf32(float x){
  float r; asm("cvt.rna.tf32.f32 %0, %1;" : "=f"(r) : "f"(x)); return r;
}

__device__ __forceinline__ void mma8(float (&c)[4], const float (&a)[4], const float (&b)[2]){
  asm volatile(
    "mma.sync.aligned.m16n8k8.row.col.f32.tf32.tf32.f32 "
    "{%0,%1,%2,%3}, {%4,%5,%6,%7}, {%8,%9}, {%0,%1,%2,%3};\n"
    : "+f"(c[0]), "+f"(c[1]), "+f"(c[2]), "+f"(c[3])
    : "r"(__float_as_uint(a[0])), "r"(__float_as_uint(a[1])),
      "r"(__float_as_uint(a[2])), "r"(__float_as_uint(a[3])),
      "r"(__float_as_uint(b[0])), "r"(__float_as_uint(b[1])));
}

__device__ __forceinline__ void cp16(float* smem_ptr, const float* gmem, bool pred){
  unsigned int s = (unsigned int)__cvta_generic_to_shared(smem_ptr);
  int sz = pred ? 16 : 0;
  asm volatile("cp.async.cg.shared.global [%0], [%1], 16, %2;\n"
               :: "r"(s), "l"(gmem), "r"(sz));
}
#define CP_COMMIT() asm volatile("cp.async.commit_group;\n")
#define CP_WAIT2()  asm volatile("cp.async.wait_group 2;\n")

// grid-stride tf32 rounding copy (n % 4 == 0)
__global__ void roundcopy_k(const float* __restrict__ src, float* __restrict__ dst, int n){
  int i = (blockIdx.x*blockDim.x + threadIdx.x)*4;
  int stride = gridDim.x*blockDim.x*4;
  for (; i+3 < n; i += stride){
    float4 v = *(const float4*)(src+i);
    float4 w; w.x=to_tf32(v.x); w.y=to_tf32(v.y); w.z=to_tf32(v.z); w.w=to_tf32(v.w);
    *(float4*)(dst+i) = w;
  }
}

// ---------------------------------------------------------------------------
// 4-stage cp.async tf32 GEMM, 512 threads = 16 warps (4m x 4n, warp 32x32).
// BM=128, BN=128, BK=16.
//  AMODE: 0 A[m*lda+k], 1 human-RF rows, 2 obj-RF rows, 3 A[k*lda+m]
//  BMODE: 0 B[k*ldb+n], 1 B[n*ldb+k]
//  CMODE: 0 crow=m, 1 crow=m*6, 2 obj row map
//  EPI:   0 none, 1 bias+relu, 2 round output to tf32
//  ACVT:  1 -> convert A-frags to tf32 in-register (A not pre-rounded)
//  Row-major tile: [128][20] ; K-major tile: [16][136]. One barrier/iter.
// ---------------------------------------------------------------------------
template<int AMODE,int BMODE,int CMODE,int EPI,int ACVT>
__global__ __launch_bounds__(512,2) void fgemm_k(GemmP p)
{
  constexpr bool AROW = (AMODE != 3);
  constexpr bool BROW = (BMODE == 1);
  constexpr int ASZ = AROW ? 128*20 : 16*136;
  constexpr int BSZ = BROW ? 128*20 : 16*136;
  extern __shared__ float dsm[];
  float* As = dsm;              // [4][ASZ]
  float* Bs = dsm + 4*ASZ;      // [4][BSZ]

  const int m0 = blockIdx.y * 128;
  const int n0 = blockIdx.x * 128;
  const int tid = threadIdx.x, wid = tid>>5, lane = tid&31;
  const int gr = lane>>2, tg = lane&3;
  const int wm = (wid&3)*32, wn = (wid>>2)*32;

  float acc[2][4][4];
#pragma unroll
  for (int i=0;i<2;i++)
#pragma unroll
    for (int j=0;j<4;j++)
#pragma unroll
      for (int r=0;r<4;r++) acc[i][j][r]=0.f;

  auto loadA = [&](int kt, int st){
    int k0 = kt*16;
    float* dst = As + st*ASZ;
    if (AROW){
      int row=tid>>2, kq=tid&3; int m=m0+row, k=k0+kq*4;
      bool pred = (m < p.M) && (k+4 <= p.K);
      size_t base = 0;
      if (pred){
        if (AMODE==0) base = (size_t)m*p.lda;
        else if (AMODE==1){ int b=m/20, tt=m-b*20; base=((size_t)(b*120+tt))*2048; }
        else { int b=m/100, rm=m-b*100; int u=1+rm/20, tt=rm-(u-1)*20;
               base=((size_t)(b*120+u*20+tt))*2048; }
      }
      cp16(dst + row*20+kq*4, pred ? (p.A+base+k) : p.A, pred);
    } else {
      int kl=tid>>5, mq=tid&31; int k=k0+kl, m=m0+mq*4;
      bool pred = (k < p.K) && (m+4 <= p.M);
      cp16(dst + kl*136+mq*4, pred ? (p.A+(size_t)k*p.lda+m) : p.A, pred);
    }
  };
  auto loadB = [&](int kt, int st){
    int k0 = kt*16;
    float* dst = Bs + st*BSZ;
    if (BROW){
      int row=tid>>2, kq=tid&3; int n=n0+row, k=k0+kq*4;
      bool pred = (n < p.N) && (k+4 <= p.K);
      cp16(dst + row*20+kq*4, pred ? (p.B+(size_t)n*p.ldb+k) : p.B, pred);
    } else {
      int kl=tid>>5, nq=tid&31; int k=k0+kl, n=n0+nq*4;
      bool pred = (k < p.K) && (n+4 <= p.N);
      cp16(dst + kl*136+nq*4, pred ? (p.B+(size_t)k*p.ldb+n) : p.B, pred);
    }
  };

  const int ntk = (p.K + 15) >> 4;
  loadA(0,0); loadB(0,0); CP_COMMIT();
  loadA(1,1); loadB(1,1); CP_COMMIT();   // kt>=ntk safely zero-fills
  loadA(2,2); loadB(2,2); CP_COMMIT();

  for (int kt=0; kt<ntk; kt++){
    const int st = kt & 3;
    CP_WAIT2();
    __syncthreads();

    const float* Ast = As + st*ASZ;
    const float* Bst = Bs + st*BSZ;
#pragma unroll
    for (int kk=0; kk<16; kk+=8){
      float a[2][4];
#pragma unroll
      for (int i=0;i<2;i++){
        int mr = wm + i*16 + gr;
        if (AROW){
          a[i][0]=Ast[ mr   *20 + kk+tg  ];
          a[i][1]=Ast[(mr+8)*20 + kk+tg  ];
          a[i][2]=Ast[ mr   *20 + kk+tg+4];
          a[i][3]=Ast[(mr+8)*20 + kk+tg+4];
        } else {
          a[i][0]=Ast[(kk+tg  )*136 + mr  ];
          a[i][1]=Ast[(kk+tg  )*136 + mr+8];
          a[i][2]=Ast[(kk+tg+4)*136 + mr  ];
          a[i][3]=Ast[(kk+tg+4)*136 + mr+8];
        }
        if (ACVT){
#pragma unroll
          for (int q=0;q<4;q++) a[i][q] = to_tf32(a[i][q]);
        }
      }
      float b[4][2];
#pragma unroll
      for (int j=0;j<4;j++){
        int nc = wn + j*8 + gr;
        if (BROW){
          b[j][0]=Bst[nc*20 + kk+tg  ];
          b[j][1]=Bst[nc*20 + kk+tg+4];
        } else {
          b[j][0]=Bst[(kk+tg  )*136 + nc];
          b[j][1]=Bst[(kk+tg+4)*136 + nc];
        }
      }
#pragma unroll
      for (int i=0;i<2;i++)
#pragma unroll
        for (int j=0;j<4;j++) mma8(acc[i][j], a[i], b[j]);
    }
    // issue tile kt+3 into stage (kt+3)&3 (consumed at iter kt-1; the iter-kt
    // barrier retired all its readers). Zero-fill past end keeps group
    // accounting in-order for CP_WAIT2.
    loadA(kt+3, (kt+3)&3); loadB(kt+3, (kt+3)&3);
    CP_COMMIT();
  }

  // ---- epilogue
#pragma unroll
  for (int i=0;i<2;i++){
#pragma unroll
    for (int r=0;r<4;r++){
      int m = m0 + wm + i*16 + gr + ((r>=2)?8:0);
      if (m >= p.M) continue;
      size_t crow;
      if (CMODE==0) crow = (size_t)m;
      else if (CMODE==1) crow = (size_t)m * 6;
      else { int b=m/100, rm=m-b*100; int u=1+rm/20, tt=rm-(u-1)*20;
             crow = ((size_t)(b*20+tt))*6 + u; }
#pragma unroll
      for (int j=0;j<4;j++){
        int n = n0 + wn + j*8 + tg*2 + (r&1);
        if (n >= p.N) continue;
        float v = acc[i][j][r];
        if (EPI==1){ v += p.bias1[n]; v = fmaxf(v, 0.f); }
        if (EPI==2){ v = to_tf32(v); }
        p.C[crow*(size_t)p.ldc + n] = v;
      }
    }
  }
}

// ---------------------------------------------------------------------------
// Persistent fused bidir RNN layer: block owns 32 rows, loops 20 steps.
// OUT written tf32-rounded (consumed only as GEMM A operands).
// ---------------------------------------------------------------------------
template<int HD>
__global__ __launch_bounds__(256) void rnnfuse_k(const float* __restrict__ XP,
    const float* __restrict__ Whh, const float* __restrict__ bih,
    const float* __restrict__ bhh, float* __restrict__ OUT, int M)
{
  constexpr int HP = HD+4;
  constexpr int BP = HD+8;
  constexpr int NJ = HD/64;
  extern __shared__ float sm[];
  float* hs  = sm;
  float* Bsm = sm + 32*HP;

  const int d  = blockIdx.z;
  const int r0 = blockIdx.x*32;
  const int tid = threadIdx.x, wid = tid>>5, lane = tid&31;
  const int gr = lane>>2, tg = lane&3;
  const int wn = wid*(HD/8);
  const float* Bp = Whh + (size_t)d*HD*HD;

  float bb[NJ][2];
#pragma unroll
  for (int j=0;j<NJ;j++){
    int n = wn + j*8 + tg*2;
    bb[j][0] = bih[d*HD+n]   + bhh[d*HD+n];
    bb[j][1] = bih[d*HD+n+1] + bhh[d*HD+n+1];
  }

  for (int s=0; s<20; s++){
    int t = d ? (19 - s) : s;
    float acc[2][NJ][4];
#pragma unroll
    for (int i=0;i<2;i++)
#pragma unroll
      for (int j=0;j<NJ;j++)
#pragma unroll
        for (int r=0;r<4;r++) acc[i][j][r]=0.f;

    if (s > 0){
      for (int k0=0; k0<HD; k0+=16){
        __syncthreads();
        for (int idx=tid; idx<HD*4; idx+=256){
          int nl=idx>>2, kq=idx&3;
          float4 v = *(const float4*)&Bp[(size_t)nl*HD + k0 + kq*4];
          Bsm[(kq*4+0)*BP + nl]=to_tf32(v.x);
          Bsm[(kq*4+1)*BP + nl]=to_tf32(v.y);
          Bsm[(kq*4+2)*BP + nl]=to_tf32(v.z);
          Bsm[(kq*4+3)*BP + nl]=to_tf32(v.w);
        }
        __syncthreads();
#pragma unroll
        for (int kk=0; kk<16; kk+=8){
          float a[2][4];
#pragma unroll
          for (int i=0;i<2;i++){
            int lr = i*16 + gr;
            a[i][0]=hs[ lr   *HP + k0+kk+tg  ];
            a[i][1]=hs[(lr+8)*HP + k0+kk+tg  ];
            a[i][2]=hs[ lr   *HP + k0+kk+tg+4];
            a[i][3]=hs[(lr+8)*HP + k0+kk+tg+4];
          }
          float b[NJ][2];
#pragma unroll
          for (int j=0;j<NJ;j++){
            int nc = wn + j*8 + gr;
            b[j][0]=Bsm[(kk+tg  )*BP + nc];
            b[j][1]=Bsm[(kk+tg+4)*BP + nc];
          }
#pragma unroll
          for (int i=0;i<2;i++)
#pragma unroll
            for (int j=0;j<NJ;j++) mma8(acc[i][j], a[i], b[j]);
        }
      }
    }
    __syncthreads();
#pragma unroll
    for (int i=0;i<2;i++)
#pragma unroll
      for (int r=0;r<4;r++){
        int lm = i*16 + gr + ((r>=2)?8:0);
        int m  = r0 + lm;
#pragma unroll
        for (int j=0;j<NJ;j++){
          int n = wn + j*8 + tg*2 + (r&1);
          if (m < M){
            size_t o = ((size_t)m*20 + t)*(size_t)(2*HD) + (size_t)d*HD + n;
            float v = to_tf32(tanhf(acc[i][j][r] + XP[o] + bb[j][r&1]));
            OUT[o] = v;
            hs[lm*HP + n] = v;
          } else {
            hs[lm*HP + n] = 0.f;
          }
        }
      }
  }
}

__global__ void chco_k(const float* bph, const float* bpo, const float* Wg1,
                       float* CHv, float* COv)
{
  __shared__ float sa[256], sc[256];
  int hl = threadIdx.x & 31, sl = threadIdx.x >> 5;
  int h = blockIdx.x*32 + hl;
  float a=0.f, c=0.f;
  for (int q=0; q<125; q++){
    int pp = sl*125 + q;
    a += bph[pp]*Wg1[(size_t)(4+pp)*512 + h];
    c += bpo[pp]*Wg1[(size_t)(1004+pp)*512 + h];
  }
  sa[threadIdx.x]=a; sc[threadIdx.x]=c;
  __syncthreads();
  if (sl==0){
    for (int s2=1;s2<8;s2++){ a+=sa[s2*32+hl]; c+=sc[s2*32+hl]; }
    CHv[h]=a; COv[h]=c;
  }
}

// mix1: slivers + A_HAT mix + bg1 + relu; output tf32-rounded
__global__ void mix1_k(const float* __restrict__ Y, const float* __restrict__ Wg1,
                       const float* __restrict__ bg1, const float* __restrict__ bbox,
                       const float* __restrict__ oh, const float* __restrict__ CHv,
                       const float* __restrict__ COv, float* __restrict__ G1)
{
  int bt = blockIdx.x; int b = bt/20, t = bt - b*20;
  __shared__ float sb[24], so[50];
  int tid = threadIdx.x;
  if (tid < 24) sb[tid] = bbox[((size_t)(b*6 + (tid>>2))*20 + t)*4 + (tid&3)];
  if (tid >= 32 && tid < 82) {
    int q = tid-32;
    so[q] = oh[((size_t)(b*5 + q/10)*20 + t)*10 + (q - (q/10)*10)];
  }
  __syncthreads();
  int h = tid;
  size_t base = (size_t)bt * 6 * 512;
  float y0 = Y[base + h] + CHv[h];
#pragma unroll
  for (int i=0;i<4;i++) y0 += sb[i]*Wg1[(size_t)i*512 + h];
  float ys = 0.f, yu[5];
#pragma unroll
  for (int u=1; u<=5; u++){
    float v = Y[base + (size_t)u*512 + h] + COv[h];
#pragma unroll
    for (int i=0;i<4;i++) v += sb[u*4+i]*Wg1[(size_t)(2004+i)*512 + h];
#pragma unroll
    for (int j=0;j<10;j++) v += so[(u-1)*10+j]*Wg1[(size_t)(2008+j)*512 + h];
    yu[u-1]=v; ys += v;
  }
  const float R6 = 1.f/6.f, R12 = 0.28867513459481287f;
  float bg = bg1[h];
  G1[base + h] = to_tf32(fmaxf(R6*y0 + R12*ys + bg, 0.f));
#pragma unroll
  for (int u=1;u<=5;u++)
    G1[base + (size_t)u*512 + h] = to_tf32(fmaxf(R12*y0 + 0.5f*yu[u-1] + bg, 0.f));
}

// mix2: A_HAT mix + bg2 + relu -> SG (rounded), HN (rounded)
__global__ void mix2_k(const float* __restrict__ Z, const float* __restrict__ bg2,
                       float* __restrict__ SG, float* __restrict__ HN)
{
  int bt = blockIdx.x;
  int h = threadIdx.x;
  size_t base = (size_t)bt*6*512;
  float z0 = Z[base+h];
  float zs=0.f, zu[5];
#pragma unroll
  for (int u=1;u<=5;u++){ float v = Z[base+(size_t)u*512+h]; zu[u-1]=v; zs+=v; }
  const float R6 = 1.f/6.f, R12 = 0.28867513459481287f;
  float bg = bg2[h];
  float g0 = to_tf32(fmaxf(R6*z0 + R12*zs + bg, 0.f));
  SG[base+h]=g0;
  HN[(size_t)bt*512+h]=g0;
#pragma unroll
  for (int u=1;u<=5;u++)
    SG[base+(size_t)u*512+h] = to_tf32(fmaxf(R12*z0 + 0.5f*zu[u-1] + bg, 0.f));
}

__global__ void prefix_k(const int* num, int* off){
  if (threadIdx.x==0){
    int a=0;
    for (int b=0;b<256;b++){ off[b]=a; a+=num[b]; }
    off[256]=a;
  }
}

__global__ void gather_k(const float* __restrict__ SG, const int* __restrict__ num,
                         const int* __restrict__ off, float* __restrict__ ON)
{
  int bk = blockIdx.x; int b = bk/5, k = bk - b*5;
  if (k >= num[b]) return;
  int t = blockIdx.y;
  int r = off[b] + k;
  size_t ob  = ((size_t)r*20 + t)*1024;
  size_t sgb = ((size_t)(b*20+t))*6*512;
  int h = threadIdx.x;
  ON[ob + h]       = SG[sgb + h];
  ON[ob + 512 + h] = SG[sgb + (size_t)(k+1)*512 + h];
}

__global__ void head_k(const float* __restrict__ A1, const float* __restrict__ W2,
                       const float* __restrict__ b2, float* __restrict__ out, int nout)
{
  int r = blockIdx.x;
  __shared__ float cs[512];
  __shared__ float red[256];
  int tid = threadIdx.x;
  for (int j = tid; j < 512; j += 256){
    float s = 0.f;
    for (int t=0;t<20;t++) s += A1[((size_t)r*20 + t)*512 + j];
    cs[j] = s;
  }
  __syncthreads();
  for (int i=0;i<nout;i++){
    float v = cs[tid]*W2[(size_t)i*512+tid] + cs[tid+256]*W2[(size_t)i*512+tid+256];
    red[tid]=v; __syncthreads();
    for (int st=128; st>0; st>>=1){ if (tid<st) red[tid]+=red[tid+st]; __syncthreads(); }
    if (tid==0) out[(size_t)r*nout + i] = red[0] + 20.f*b2[i];
    __syncthreads();
  }
}

// ------------------------------- host side ---------------------------------
template<int AM,int BM2,int CM,int EP,int AC>
static inline void launch_f(const GemmP& p){
  constexpr int ASZ = (AM!=3) ? 128*20 : 16*136;
  constexpr int BSZ = (BM2==1) ? 128*20 : 16*136;
  constexpr int SMB = 4*(ASZ+BSZ)*4;
  cudaFuncSetAttribute(fgemm_k<AM,BM2,CM,EP,AC>,
                       cudaFuncAttributeMaxDynamicSharedMemorySize, SMB);
  dim3 g((unsigned)((p.N+127)/128), (unsigned)((p.M+127)/128), 1);
  fgemm_k<AM,BM2,CM,EP,AC><<<g,512,SMB>>>(p);
}

extern "C" void kernel_launch(void* const* d_in, const int* in_sizes, int n_in,
                              void* d_out, int out_size)
{
  const float* one_hot = (const float*)d_in[0];
  const float* bbox    = (const float*)d_in[1];
  const int*   numobj  = (const int*)  d_in[2];
  const float* rf      = (const float*)d_in[3];
  const float* Wph  = (const float*)d_in[4];
  const float* bph  = (const float*)d_in[5];
  const float* Wpo  = (const float*)d_in[6];
  const float* bpo  = (const float*)d_in[7];
  const float* Wg1  = (const float*)d_in[8];
  const float* bg1  = (const float*)d_in[9];
  const float* Wg2  = (const float*)d_in[10];
  const float* bg2  = (const float*)d_in[11];
  const float* sWih = (const float*)d_in[12];
  const float* sWhh = (const float*)d_in[13];
  const float* sbih = (const float*)d_in[14];
  const float* sbhh = (const float*)d_in[15];
  const float* aWih = (const float*)d_in[16];
  const float* aWhh = (const float*)d_in[17];
  const float* abih = (const float*)d_in[18];
  const float* abhh = (const float*)d_in[19];
  const float* chW1 = (const float*)d_in[20];
  const float* chb1 = (const float*)d_in[21];
  const float* chW2 = (const float*)d_in[22];
  const float* chb2 = (const float*)d_in[23];
  const float* coW1 = (const float*)d_in[24];
  const float* cob1 = (const float*)d_in[25];
  const float* coW2 = (const float*)d_in[26];
  const float* cob2 = (const float*)d_in[27];
  float* out = (float*)d_out;

  int Ntot = (out_size - 2560) / 12;
  if (Ntot < 0) Ntot = 0; if (Ntot > 1280) Ntot = 1280;

  float *MH,*MO,*CHv,*COv,*Y,*G1,*Z,*SG,*HN,*ON,*XPH,*HR0,*HR1,*XPO,*OR0,*OR1,*A1H,*A1O;
  float *Wphr,*Wpor,*Wg1r,*Wg2r,*sWihr,*aWihr,*chW1r,*coW1r;
  int *off;
  cudaGetSymbolAddress((void**)&MH,  g_MH);
  cudaGetSymbolAddress((void**)&MO,  g_MO);
  cudaGetSymbolAddress((void**)&CHv, g_CHv);
  cudaGetSymbolAddress((void**)&COv, g_COv);
  cudaGetSymbolAddress((void**)&Y,   g_Y);
  cudaGetSymbolAddress((void**)&G1,  g_G1);
  cudaGetSymbolAddress((void**)&Z,   g_Z);
  cudaGetSymbolAddress((void**)&SG,  g_SG);
  cudaGetSymbolAddress((void**)&HN,  g_HN);
  cudaGetSymbolAddress((void**)&ON,  g_ON);
  cudaGetSymbolAddress((void**)&XPH, g_XPH);
  cudaGetSymbolAddress((void**)&HR0, g_HR0);
  cudaGetSymbolAddress((void**)&HR1, g_HR1);
  cudaGetSymbolAddress((void**)&XPO, g_XPO);
  cudaGetSymbolAddress((void**)&OR0, g_OR0);
  cudaGetSymbolAddress((void**)&OR1, g_OR1);
  cudaGetSymbolAddress((void**)&A1H, g_A1H);
  cudaGetSymbolAddress((void**)&A1O, g_A1O);
  cudaGetSymbolAddress((void**)&off, g_off);
  cudaGetSymbolAddress((void**)&Wphr, g_Wphr);
  cudaGetSymbolAddress((void**)&Wpor, g_Wpor);
  cudaGetSymbolAddress((void**)&Wg1r, g_Wg1r);
  cudaGetSymbolAddress((void**)&Wg2r, g_Wg2r);
  cudaGetSymbolAddress((void**)&sWihr,g_sWihr);
  cudaGetSymbolAddress((void**)&aWihr,g_aWihr);
  cudaGetSymbolAddress((void**)&chW1r,g_chW1r);
  cudaGetSymbolAddress((void**)&coW1r,g_coW1r);

  const int SMEM512 = 32*(512+4)*4 + 16*(512+8)*4;  // 99,328 B
  const int SMEM256 = 32*(256+4)*4 + 16*(256+8)*4;  // 50,176 B
  cudaFuncSetAttribute(rnnfuse_k<512>, cudaFuncAttributeMaxDynamicSharedMemorySize, SMEM512);
  cudaFuncSetAttribute(rnnfuse_k<256>, cudaFuncAttributeMaxDynamicSharedMemorySize, SMEM256);

  // ---- pre-round weight operands (rf stays raw, ACVT handles it)
  roundcopy_k<<<256,256>>>(Wph,  Wphr, 2048000);
  roundcopy_k<<<256,256>>>(Wpo,  Wpor, 2048000);
  roundcopy_k<<<256,256>>>(Wg1,  Wg1r, 1033216);
  roundcopy_k<<<64,256>>>(Wg2,  Wg2r, 262144);
  roundcopy_k<<<64,256>>>(sWih, sWihr,524288);
  roundcopy_k<<<256,256>>>(aWih, aWihr,2097152);
  roundcopy_k<<<64,256>>>(chW1, chW1r,262144);
  roundcopy_k<<<64,256>>>(coW1, coW1r,524288);

  // MH = Wph^T @ Wg1[4:1004] ; MO = Wpo^T @ Wg1[1004:2004]  (outputs rounded)
  { GemmP p{}; p.A=Wphr; p.lda=2048; p.B=Wg1r+4*512; p.ldb=512;
    p.C=MH; p.ldc=512; p.M=2048; p.N=512; p.K=1000; launch_f<3,0,0,2,0>(p); }
  { GemmP p{}; p.A=Wpor; p.lda=2048; p.B=Wg1r+1004*512; p.ldb=512;
    p.C=MO; p.ldc=512; p.M=2048; p.N=512; p.K=1000; launch_f<3,0,0,2,0>(p); }
  chco_k<<<16,256>>>(bph, bpo, Wg1, CHv, COv);

  // Y = rf @ M  (written [b,t,u,512]); rf raw -> ACVT=1
  { GemmP p{}; p.A=rf; p.B=MH; p.ldb=512;
    p.C=Y; p.ldc=512; p.M=5120; p.N=512; p.K=2048; launch_f<1,0,1,0,1>(p); }
  { GemmP p{}; p.A=rf; p.B=MO; p.ldb=512;
    p.C=Y; p.ldc=512; p.M=25600; p.N=512; p.K=2048; launch_f<2,0,2,0,1>(p); }
  mix1_k<<<5120,512>>>(Y, Wg1, bg1, bbox, one_hot, CHv, COv, G1);

  // Z = G1 @ Wg2 -> mix2 -> SG, HN
  { GemmP p{}; p.A=G1; p.lda=512; p.B=Wg2r; p.ldb=512;
    p.C=Z; p.ldc=512; p.M=30720; p.N=512; p.K=512; launch_f<0,0,0,0,0>(p); }
  mix2_k<<<5120,512>>>(Z, bg2, SG, HN);

  prefix_k<<<1,32>>>(numobj, off);
  gather_k<<<dim3(1280,20),512>>>(SG, numobj, off, ON);

  // human bidir RNN (hidden 256/dir)
  for (int l=0;l<2;l++){
    GemmP p{}; p.A = (l==0)?HN:HR0; p.lda=512;
    p.B = sWihr + (size_t)l*2*256*512; p.ldb=512;
    p.C = XPH; p.ldc=512; p.M=5120; p.N=512; p.K=512;
    launch_f<0,1,0,0,0>(p);
    float* HRl = (l==0)?HR0:HR1;
    rnnfuse_k<256><<<dim3(8,1,2),256,SMEM256>>>(
        XPH, sWhh + (size_t)l*2*256*256,
        sbih + (size_t)l*2*256, sbhh + (size_t)l*2*256, HRl, 256);
  }

  // object bidir RNN (hidden 512/dir)
  if (Ntot > 0) {
    int rb = (Ntot + 31)/32;
    for (int l=0;l<2;l++){
      GemmP p{}; p.A = (l==0)?ON:OR0; p.lda=1024;
      p.B = aWihr + (size_t)l*2*512*1024; p.ldb=1024;
      p.C = XPO; p.ldc=1024; p.M=Ntot*20; p.N=1024; p.K=1024;
      launch_f<0,1,0,0,0>(p);
      float* ORl = (l==0)?OR0:OR1;
      rnnfuse_k<512><<<dim3(rb,1,2),256,SMEM512>>>(
          XPO, aWhh + (size_t)l*2*512*512,
          abih + (size_t)l*2*512, abhh + (size_t)l*2*512, ORl, Ntot);
    }
  }

  // heads
  { GemmP p{}; p.A=HR1; p.lda=512; p.B=chW1r; p.ldb=512;
    p.C=A1H; p.ldc=512; p.M=5120; p.N=512; p.K=512;
    p.bias1=chb1; launch_f<0,1,0,1,0>(p); }
  head_k<<<256,256>>>(A1H, chW2, chb2, out, 10);

  if (Ntot > 0) {
    GemmP p{}; p.A=OR1; p.lda=1024; p.B=coW1r; p.ldb=1024;
    p.C=A1O; p.ldc=512; p.M=Ntot*20; p.N=512; p.K=1024;
    p.bias1=cob1; launch_f<0,1,0,1,0>(p);
    head_k<<<Ntot,256>>>(A1O, coW2, cob2, out + 2560, 12);
  }
}